// round 17
// baseline (speedup 1.0000x reference)
#include <cuda_runtime.h>
#include <cuda_fp16.h>
#include <math.h>

#ifndef M_PI
#define M_PI 3.14159265358979323846
#endif

#define NA   1152
#define ND   736
#define NP   512
#define PADN 2048
#define HALF_SPEC (PADN/2 + 1)
#define ESZ  1476      // extended filter: s_e[i] = h[(i-736) mod 2048]
#define RS   1280      // padded row stride (entries); index range [-256, 1024)
#define ROFF 256       // entry offset: entry = i0 + ROFF

// ---- device scratch (static allocations only; zero-initialized at load) ----
__device__ float   g_filt[HALF_SPEC];  // rfft half-spectrum filter
__device__ float   g_h[PADN];          // spatial filter (A*D^2, pi/2NA folded in)
__device__ float4  g_ang[NA];          // (cos, sin, K*cos, K*sin) per angle
__device__ __half2 g_ph[NA * RS];      // padded pair table; pads stay (0,0) forever

// ---------------------------------------------------------------------------
__device__ __forceinline__ double block_reduce128(double v) {
    __shared__ double s[4];
    int lane = threadIdx.x & 31, w = threadIdx.x >> 5;
    #pragma unroll
    for (int o = 16; o > 0; o >>= 1)
        v += __shfl_down_sync(0xffffffffu, v, o);
    if (lane == 0) s[w] = v;
    __syncthreads();
    double t = 0.0;
    if (threadIdx.x == 0) {
        #pragma unroll
        for (int i = 0; i < 4; i++) t += s[i];
    }
    return t;
}

// ---------------------------------------------------------------------------
// FILT[k] = 2*(0.25 + 2*sum_{odd n<=1023} (-1/(pi n)^2) cos(2 pi k n / 2048))
//           * (k==0 ? 1 : sin(pi k/2048)/(pi k/2048))
__global__ void k_filt_coeff() {
    int k = blockIdx.x;  // 0..1024
    double p = 0.0;
    for (int n = 2 * threadIdx.x + 1; n < 1024; n += 256) {
        int m = (k * n) & (PADN - 1);                 // exact reduction mod 2048
        float c = cospif((float)m * (1.0f / 1024.0f));
        p += (double)(c / ((float)n * (float)n));
    }
    double s = block_reduce128(p);
    if (threadIdx.x == 0) {
        const double inv_pi2 = 1.0 / (M_PI * M_PI);
        double F = 2.0 * (0.25 - 2.0 * inv_pi2 * s);
        if (k > 0) {
            double x = M_PI * (double)k / (double)PADN;
            F *= sin(x) / x;
        }
        g_filt[k] = (float)F;
    }
}

// h[n] = irdft(FILT)[n], scaled by pi/(2*NA) * A * D^2  (A = HU rescale slope)
__global__ void k_spatial() {
    int n = blockIdx.x;  // 0..2047
    double p = 0.0;
    for (int k = threadIdx.x + 1; k < PADN / 2; k += 128) {
        int m = (k * n) & (PADN - 1);
        float c = cospif((float)m * (1.0f / 1024.0f));
        p += (double)(g_filt[k] * c);
    }
    double s = block_reduce128(p);
    if (threadIdx.x == 0) {
        double v = (double)g_filt[0] + 2.0 * s
                 + (double)g_filt[PADN / 2] * ((n & 1) ? -1.0 : 1.0);
        const double Dd = (1.0 / 0.7) * 595.0;
        const double A  = 1000.0 / (0.0192 * 4096.0);
        v *= (1.0 / (double)PADN) * (M_PI / (2.0 * (double)NA)) * A * Dd * Dd;
        g_h[n] = (float)v;
    }
}

__global__ void k_angles() {
    int a = blockIdx.x * blockDim.x + threadIdx.x;
    if (a < NA) {
        double ang = (2.0 * M_PI / (double)NA) * (double)a + M_PI / 2.0;
        double K = ((595.0 + 490.6) / 1.2858);   // DSD/DU (VOX cancels)
        float c = (float)cos(ang), s = (float)sin(ang);
        g_ang[a] = make_float4(c, s, (float)(K * cos(ang)), (float)(K * sin(ang)));
    }
}

// ---------------------------------------------------------------------------
// Per-row circular convolution (round-5 scalar inner loop, conflict-free)
// + half2 pair epilogue into the zero-padded table.
__global__ void __launch_bounds__(256) k_conv(const float* __restrict__ sino) {
    __shared__ float s_row[ND];
    __shared__ float s_e[ESZ];          // s_e[i] = h[(i - 736) mod 2048]
    __shared__ float s_out[ND];
    int a = blockIdx.x;
    const float* row = sino + a * ND;
    for (int i = threadIdx.x; i < ND; i += blockDim.x)  s_row[i] = row[i];
    for (int i = threadIdx.x; i < ESZ; i += blockDim.x) s_e[i] = g_h[(i + 1312) & (PADN - 1)];
    __syncthreads();

    int j0 = 3 * threadIdx.x;
    if (j0 < ND) {
        const float* e = s_e + (j0 + 736);  // e[-m] = h[(j0-m) & 2047]
        float a0 = 0.f, a1 = 0.f, a2 = 0.f;
        float hm  = e[0];
        float hm1 = e[1];
        float hm2 = e[2];
        #pragma unroll 4
        for (int m = 0; m < ND; m++) {
            float r = s_row[m];
            a0 = fmaf(r, hm,  a0);
            a1 = fmaf(r, hm1, a1);
            a2 = fmaf(r, hm2, a2);
            hm2 = hm1; hm1 = hm;
            hm = e[-m - 1];
        }
        s_out[j0] = a0;
        if (j0 + 1 < ND) s_out[j0 + 1] = a1;
        if (j0 + 2 < ND) s_out[j0 + 2] = a2;
    }
    __syncthreads();

    // pair entries i in [0, 735): (v[i], v[i+1]); entry 735 and pads stay zero
    __half2* dst = g_ph + a * RS + ROFF;
    for (int i = threadIdx.x; i < ND - 1; i += blockDim.x)
        dst[i] = __floats2half2_rn(s_out[i], s_out[i + 1]);
}

// ---------------------------------------------------------------------------
// Pixel-driven fan-beam backprojection. 8 angles/iter, ONE LDG.32 per angle
// (half2 pair from zero-padded table) — no clamp, no validity select:
// out-of-range i0 hits zero pairs, contributing exactly 0 (reference semantics).
__global__ void __launch_bounds__(256) k_bp(float* __restrict__ out) {
    __shared__ float4 s_ang[NA];
    for (int t = threadIdx.y * blockDim.x + threadIdx.x; t < NA;
         t += blockDim.x * blockDim.y)
        s_ang[t] = g_ang[t];
    __syncthreads();

    int j = blockIdx.x * blockDim.x + threadIdx.x;  // x (fast dim)
    int i = blockIdx.y * blockDim.y + threadIdx.y;  // y (slow dim)
    float x = (float)j - 255.5f;
    float y = (float)i - 255.5f;

    const float Df = (float)((1.0 / 0.7) * 595.0);
    const float CD = 367.5f;                         // (ND-1)/2

    const __half2* __restrict__ ph = g_ph;
    float acc0 = 0.f, acc1 = 0.f, acc2 = 0.f, acc3 = 0.f;

    for (int a = 0; a < NA; a += 8) {
        int   off[8];
        float fr[8], wv[8];
        #pragma unroll
        for (int q = 0; q < 8; q++) {
            float4 tq = s_ang[a + q];
            float den = fmaf(-y, tq.y, fmaf(-x, tq.x, Df));
            float pe  = fmaf(y, tq.z, -x * tq.w);    // K*(y*cos - x*sin)
            float rcp;
            asm("rcp.approx.f32 %0, %1;" : "=f"(rcp) : "f"(den));
            float iu  = fmaf(pe, rcp, CD);
            int   i0  = __float2int_rd(iu);          // in [-256, 991] always
            fr[q]  = iu - __int2float_rn(i0);
            off[q] = (a + q) * RS + (i0 + ROFF);     // always in-bounds
            wv[q]  = rcp * rcp;                      // invalid -> zero pair anyway
        }
        __half2 hv[8];
        #pragma unroll
        for (int q = 0; q < 8; q++) hv[q] = __ldg(ph + off[q]);
        #pragma unroll
        for (int q = 0; q < 8; q += 4) {
            float2 v0 = __half22float2(hv[q]);
            float2 v1 = __half22float2(hv[q + 1]);
            float2 v2 = __half22float2(hv[q + 2]);
            float2 v3 = __half22float2(hv[q + 3]);
            acc0 = fmaf(wv[q],     fmaf(fr[q],     v0.y - v0.x, v0.x), acc0);
            acc1 = fmaf(wv[q + 1], fmaf(fr[q + 1], v1.y - v1.x, v1.x), acc1);
            acc2 = fmaf(wv[q + 2], fmaf(fr[q + 2], v2.y - v2.x, v2.x), acc2);
            acc3 = fmaf(wv[q + 3], fmaf(fr[q + 3], v3.y - v3.x, v3.x), acc3);
        }
    }
    float acc = (acc0 + acc1) + (acc2 + acc3);

    const float B = (float)(24.0 / 4096.0);
    out[i * NP + j] = acc + B;
}

// ---------------------------------------------------------------------------
extern "C" void kernel_launch(void* const* d_in, const int* in_sizes, int n_in,
                              void* d_out, int out_size) {
    const float* x = (const float*)d_in[0];   // (1,1,1152,736) f32
    float* out = (float*)d_out;               // (1,1,512,512) f32

    k_filt_coeff<<<HALF_SPEC, 128>>>();
    k_spatial<<<PADN, 128>>>();
    k_angles<<<(NA + 255) / 256, 256>>>();
    k_conv<<<NA, 256>>>(x);
    dim3 bb(32, 8), gb(NP / 32, NP / 8);
    k_bp<<<gb, bb>>>(out);
}